// round 13
// baseline (speedup 1.0000x reference)
#include <cuda_runtime.h>
#include <cuda_fp16.h>
#include <cstdint>

#define MAXN 100000
#define MAXE 1600000
#define F 128
#define CAP 96       // fixed CSR slot capacity per node (P(deg>96) ~ 0)
#define SPITCH 136   // halfs per smem row (conflict-free LDS + LDSM)

// -------- scratch ----------
__device__ int    g_cur[MAXN];                    // in-degree counters / cursors
__device__ int    g_csr[(size_t)MAXN * CAP];      // slotted CSR
__device__ float  g_dinv[MAXN];
__device__ float  g_s[MAXN];
__device__ float  g_bvec[F];
__device__ __half g_whi[F * F];                   // Wc' in B layout: [n][k]
__device__ __half g_t[(size_t)MAXN * F];          // x @ Wc' (UNSCALED, fp16)
__device__ __half g_t2[(size_t)MAXN * F];         // prescaled agg result

__device__ __forceinline__ void acc_h4(float4& acc, uint2 p) {
    float2 f0 = __half22float2(*(__half2*)&p.x);
    float2 f1 = __half22float2(*(__half2*)&p.y);
    acc.x += f0.x; acc.y += f0.y; acc.z += f1.x; acc.w += f1.y;
}
// fused: acc += s * p
__device__ __forceinline__ void acc_h4f(float4& acc, uint2 p, float s) {
    float2 f0 = __half22float2(*(__half2*)&p.x);
    float2 f1 = __half22float2(*(__half2*)&p.y);
    acc.x = fmaf(f0.x, s, acc.x); acc.y = fmaf(f0.y, s, acc.y);
    acc.z = fmaf(f1.x, s, acc.z); acc.w = fmaf(f1.y, s, acc.w);
}

__device__ __forceinline__ void mma16816(
    float& d0, float& d1, float& d2, float& d3,
    uint32_t a0, uint32_t a1, uint32_t a2, uint32_t a3,
    uint32_t b0, uint32_t b1)
{
    asm volatile(
        "mma.sync.aligned.m16n8k16.row.col.f32.f16.f16.f32 "
        "{%0,%1,%2,%3}, {%4,%5,%6,%7}, {%8,%9}, {%0,%1,%2,%3};"
        : "+f"(d0), "+f"(d1), "+f"(d2), "+f"(d3)
        : "r"(a0), "r"(a1), "r"(a2), "r"(a3), "r"(b0), "r"(b1));
}
__device__ __forceinline__ void ldsm_x4(
    uint32_t& r0, uint32_t& r1, uint32_t& r2, uint32_t& r3, uint32_t addr)
{
    asm volatile(
        "ldmatrix.sync.aligned.m8n8.x4.shared.b16 {%0,%1,%2,%3}, [%4];"
        : "=r"(r0), "=r"(r1), "=r"(r2), "=r"(r3) : "r"(addr));
}

// --------------------------------------------------------------------------
// fill slotted CSR: 4 edges per thread via int4
__global__ void k_fill(const int* __restrict__ ei, int E) {
    int t = blockIdx.x * blockDim.x + threadIdx.x;
    int e4 = t * 4;
    if (e4 + 4 <= E) {
        int4 s = *(const int4*)(ei + e4);
        int4 d = *(const int4*)(ei + E + e4);
        int p0 = atomicAdd(&g_cur[d.x], 1);
        int p1 = atomicAdd(&g_cur[d.y], 1);
        int p2 = atomicAdd(&g_cur[d.z], 1);
        int p3 = atomicAdd(&g_cur[d.w], 1);
        g_csr[(size_t)d.x * CAP + p0] = s.x;
        g_csr[(size_t)d.y * CAP + p1] = s.y;
        g_csr[(size_t)d.z * CAP + p2] = s.z;
        g_csr[(size_t)d.w * CAP + p3] = s.w;
    } else {
        for (int e = e4; e < E; e++) {
            int dd = ei[E + e];
            int p = atomicAdd(&g_cur[dd], 1);
            g_csr[(size_t)dd * CAP + p] = ei[e];
        }
    }
}

__global__ void k_dinv(int n) {
    int i = blockIdx.x * blockDim.x + threadIdx.x;
    if (i < n) g_dinv[i] = rsqrtf((float)(g_cur[i] + 1));
}

// -------- Wc' = W1 @ [Wmu|Wls] -> [n][k] f16; bvec = b1 @ Wc --------------
__global__ void k_wc(const float* __restrict__ W1, const float* __restrict__ Wmu,
                     const float* __restrict__ Wls, const float* __restrict__ b1)
{
    int idx = blockIdx.x * blockDim.x + threadIdx.x;
    if (idx < F * F) {
        int k = idx >> 7, j = idx & 127;
        const float* wc = (j < 64) ? (Wmu + j) : (Wls + j - 64);
        const float* w1 = W1 + k * F;
        float s = 0.f;
        #pragma unroll 8
        for (int m = 0; m < F; m++) s = fmaf(w1[m], wc[m * 64], s);
        g_whi[j * F + k] = __float2half_rn(s);
    } else if (idx < F * F + F) {
        int j = idx - F * F;
        const float* wc = (j < 64) ? (Wmu + j) : (Wls + j - 64);
        float s = 0.f;
        #pragma unroll 8
        for (int m = 0; m < F; m++) s = fmaf(b1[m], wc[m * 64], s);
        g_bvec[j] = s;
    }
}

// -------- HMMA GEMM: t = half(x @ Wc'), 64-row tiles, ldmatrix ------------
// warp grid 4x2: wy = wid&3 -> 16 rows, wx = wid>>2 -> 64 cols.
#define HG_SMEM ((128 + 64) * SPITCH * 2)

__global__ void __launch_bounds__(256, 3) k_hgemm(
    const float* __restrict__ A, __half* __restrict__ C, int M)
{
    extern __shared__ __half smem[];
    __half* sB = smem;                  // [128][SPITCH]
    __half* sA = sB + 128 * SPITCH;     // [64][SPITCH]

    int tid = threadIdx.x;
    int row0 = blockIdx.x * 64;

    for (int i = tid * 4; i < F * F; i += 256 * 4) {
        int n = i >> 7, k = i & 127;
        *(uint2*)(sB + n * SPITCH + k) = *(const uint2*)(g_whi + i);
    }
    for (int i = tid * 4; i < 64 * F; i += 256 * 4) {
        int r = i >> 7, k = i & 127;
        float4 v = make_float4(0.f, 0.f, 0.f, 0.f);
        if (row0 + r < M)
            v = *(const float4*)(A + (size_t)(row0 + r) * F + k);
        __half2 h0 = __floats2half2_rn(v.x, v.y);
        __half2 h1 = __floats2half2_rn(v.z, v.w);
        uint2 o;
        o.x = *(uint32_t*)&h0; o.y = *(uint32_t*)&h1;
        *(uint2*)(sA + r * SPITCH + k) = o;
    }
    __syncthreads();

    int wid = tid >> 5, lane = tid & 31;
    int qr = lane >> 2, qc = lane & 3;
    int wy = wid & 3, wx = wid >> 2;
    int rb = wy * 16;                   // warp's row base (0..48)
    int cb = wx * 64;                   // warp's col base (0 or 64)

    // ldmatrix lane->address bases
    int li = lane & 7;                  // row within 8x8 matrix
    int lm = lane >> 3;                 // matrix index 0..3
    // A x4: m0=(r+0,klo) m1=(r+8,klo) m2=(r+0,khi) m3=(r+8,khi)
    uint32_t a_base = (uint32_t)__cvta_generic_to_shared(
        sA + (rb + (lm & 1) * 8 + li) * SPITCH + (lm >> 1) * 8);
    // B x4 per n-pair p: m0=(t,klo) m1=(t,khi) m2=(t+1,klo) m3=(t+1,khi)
    uint32_t b_base[4];
    #pragma unroll
    for (int p = 0; p < 4; p++)
        b_base[p] = (uint32_t)__cvta_generic_to_shared(
            sB + (cb + p * 16 + (lm >> 1) * 8 + li) * SPITCH + (lm & 1) * 8);

    float acc[8][4];
    #pragma unroll
    for (int t = 0; t < 8; t++)
        #pragma unroll
        for (int c = 0; c < 4; c++) acc[t][c] = 0.f;

    #pragma unroll
    for (int ks = 0; ks < 8; ks++) {
        uint32_t koff = ks * 16 * 2;    // bytes
        uint32_t a0, a1, a2, a3;
        ldsm_x4(a0, a1, a2, a3, a_base + koff);
        #pragma unroll
        for (int p = 0; p < 4; p++) {
            uint32_t b0, b1, b2, b3;
            ldsm_x4(b0, b1, b2, b3, b_base[p] + koff);
            mma16816(acc[2*p][0], acc[2*p][1], acc[2*p][2], acc[2*p][3],
                     a0, a1, a2, a3, b0, b1);
            mma16816(acc[2*p+1][0], acc[2*p+1][1], acc[2*p+1][2], acc[2*p+1][3],
                     a0, a1, a2, a3, b2, b3);
        }
    }

    int r1 = row0 + rb + qr;
    int r2 = r1 + 8;
    #pragma unroll
    for (int t = 0; t < 8; t++) {
        int col = cb + t * 8 + qc * 2;
        if (r1 < M) {
            __half2 h = __floats2half2_rn(acc[t][0], acc[t][1]);
            *(uint32_t*)(C + (size_t)r1 * F + col) = *(uint32_t*)&h;
        }
        if (r2 < M) {
            __half2 h = __floats2half2_rn(acc[t][2], acc[t][3]);
            *(uint32_t*)(C + (size_t)r2 * F + col) = *(uint32_t*)&h;
        }
    }
}

// -------- aggregation A (scales gathered rows by dinv[src]) ---------------
__global__ void __launch_bounds__(256) k_aggA(
    const __half* __restrict__ feat, __half* __restrict__ out, int N)
{
    int w = (blockIdx.x * blockDim.x + threadIdx.x) >> 5;
    int lane = threadIdx.x & 31;
    if (w >= N) return;
    const uint2* f2 = (const uint2*)feat;
    float dv = g_dinv[w];
    float4 acc = make_float4(0.f, 0.f, 0.f, 0.f);
    acc_h4f(acc, f2[(size_t)w * 32 + lane], dv);   // self
    float sd = 0.f;
    const int* row = g_csr + (size_t)w * CAP;
    int cnt = g_cur[w];
    int e = 0;
    for (; e + 4 <= cnt; e += 4) {
        int s0 = row[e], s1 = row[e + 1], s2 = row[e + 2], s3 = row[e + 3];
        uint2 v0 = f2[(size_t)s0 * 32 + lane];
        uint2 v1 = f2[(size_t)s1 * 32 + lane];
        uint2 v2 = f2[(size_t)s2 * 32 + lane];
        uint2 v3 = f2[(size_t)s3 * 32 + lane];
        float d0 = g_dinv[s0], d1 = g_dinv[s1], d2 = g_dinv[s2], d3 = g_dinv[s3];
        sd += d0 + d1 + d2 + d3;
        acc_h4f(acc, v0, d0); acc_h4f(acc, v1, d1);
        acc_h4f(acc, v2, d2); acc_h4f(acc, v3, d3);
    }
    for (; e < cnt; e++) {
        int s = row[e];
        float ds = g_dinv[s];
        sd += ds;
        acc_h4f(acc, f2[(size_t)s * 32 + lane], ds);
    }
    float d2 = dv * dv;
    __half2 h0 = __floats2half2_rn(acc.x * d2, acc.y * d2);
    __half2 h1 = __floats2half2_rn(acc.z * d2, acc.w * d2);
    uint2 o; o.x = *(unsigned*)&h0; o.y = *(unsigned*)&h1;
    ((uint2*)out)[(size_t)w * 32 + lane] = o;
    if (lane == 0) g_s[w] = dv * (dv + sd);
}

// -------- aggregation B + bias + reparametrize ----------
__global__ void __launch_bounds__(256) k_aggB(
    const __half* __restrict__ feat, const float* __restrict__ bmu,
    const float* __restrict__ bls, const float* __restrict__ init,
    float* __restrict__ out, int N)
{
    int w = (blockIdx.x * blockDim.x + threadIdx.x) >> 5;
    int lane = threadIdx.x & 31;
    if (w >= N) return;
    const uint2* f2 = (const uint2*)feat;
    float4 acc = make_float4(0.f, 0.f, 0.f, 0.f);
    acc_h4(acc, f2[(size_t)w * 32 + lane]);   // self (prescaled)
    const int* row = g_csr + (size_t)w * CAP;
    int cnt = g_cur[w];
    int e = 0;
    for (; e + 4 <= cnt; e += 4) {
        int s0 = row[e], s1 = row[e + 1], s2 = row[e + 2], s3 = row[e + 3];
        uint2 v0 = f2[(size_t)s0 * 32 + lane];
        uint2 v1 = f2[(size_t)s1 * 32 + lane];
        uint2 v2 = f2[(size_t)s2 * 32 + lane];
        uint2 v3 = f2[(size_t)s3 * 32 + lane];
        acc_h4(acc, v0); acc_h4(acc, v1); acc_h4(acc, v2); acc_h4(acc, v3);
    }
    for (; e < cnt; e++)
        acc_h4(acc, f2[(size_t)row[e] * 32 + lane]);

    float dv = g_dinv[w];
    float si = g_s[w];
    float4 b = (lane < 16) ? ((const float4*)bmu)[lane]
                           : ((const float4*)bls)[lane - 16];
    float4 bv = ((const float4*)g_bvec)[lane];
    float4 v = make_float4(acc.x * dv + si * bv.x + b.x,
                           acc.y * dv + si * bv.y + b.y,
                           acc.z * dv + si * bv.z + b.z,
                           acc.w * dv + si * bv.w + b.w);
    float lx = __shfl_xor_sync(0xffffffffu, v.x, 16);
    float ly = __shfl_xor_sync(0xffffffffu, v.y, 16);
    float lz = __shfl_xor_sync(0xffffffffu, v.z, 16);
    float lw = __shfl_xor_sync(0xffffffffu, v.w, 16);
    if (lane < 16) {
        float4 id = ((const float4*)init)[(size_t)w * 16 + lane];
        float4 r = make_float4(v.x + id.x * expf(lx),
                               v.y + id.y * expf(ly),
                               v.z + id.z * expf(lz),
                               v.w + id.w * expf(lw));
        ((float4*)out)[(size_t)w * 16 + lane] = r;
    }
}

// --------------------------------------------------------------------------
extern "C" void kernel_launch(void* const* d_in, const int* in_sizes, int n_in,
                              void* d_out, int out_size)
{
    const float* x    = (const float*)d_in[0];
    const int*   ei   = (const int*)d_in[1];
    const float* init = (const float*)d_in[2];
    const float* W1   = (const float*)d_in[3];
    const float* b1   = (const float*)d_in[4];
    const float* Wmu  = (const float*)d_in[5];
    const float* bmu  = (const float*)d_in[6];
    const float* Wls  = (const float*)d_in[7];
    const float* bls  = (const float*)d_in[8];
    float* out = (float*)d_out;

    int N = in_sizes[0] / F;
    int E = in_sizes[1] / 2;
    int ne4 = (E / 4 + 255) / 256;

    static cudaStream_t s2 = nullptr;
    static cudaEvent_t evFork = nullptr, evJoin = nullptr;
    if (!s2) {
        cudaStreamCreate(&s2);
        cudaEventCreateWithFlags(&evFork, cudaEventDisableTiming);
        cudaEventCreateWithFlags(&evJoin, cudaEventDisableTiming);
        cudaFuncSetAttribute(k_hgemm,
            cudaFuncAttributeMaxDynamicSharedMemorySize, HG_SMEM);
    }

    int *cur; __half *t, *t2;
    cudaGetSymbolAddress((void**)&cur, g_cur);
    cudaGetSymbolAddress((void**)&t,  g_t);
    cudaGetSymbolAddress((void**)&t2, g_t2);

    // fork: CSR build chain on s2, concurrent with wc+hgemm on main stream
    cudaEventRecord(evFork, 0);
    cudaStreamWaitEvent(s2, evFork, 0);
    cudaMemsetAsync(cur, 0, (size_t)N * sizeof(int), s2);
    k_fill<<<ne4, 256, 0, s2>>>(ei, E);
    k_dinv<<<(N + 255) / 256, 256, 0, s2>>>(N);
    cudaEventRecord(evJoin, s2);

    // main stream: weights + GEMM (independent of graph now)
    k_wc<<<(F * F + F + 255) / 256, 256>>>(W1, Wmu, Wls, b1);
    int gemm_grid = (N + 63) / 64;
    k_hgemm<<<gemm_grid, 256, HG_SMEM>>>(x, t, N);

    // join, then aggregations
    cudaStreamWaitEvent(0, evJoin, 0);
    int agg_grid = (N * 32 + 255) / 256;
    k_aggA<<<agg_grid, 256>>>(t, t2, N);
    k_aggB<<<agg_grid, 256>>>(t2, bmu, bls, init, out, N);
}

// round 14
// speedup vs baseline: 1.0916x; 1.0916x over previous
#include <cuda_runtime.h>
#include <cuda_fp16.h>
#include <cstdint>

#define MAXN 100000
#define MAXE 1600000
#define F 128
#define CAP 96       // fixed CSR slot capacity per node (P(deg>96) ~ 0)
#define SPITCH 136   // halfs per smem row (conflict-free LDS + LDSM)

// -------- scratch ----------
__device__ int    g_cur[MAXN];                    // in-degree counters / cursors
__device__ int    g_csr[(size_t)MAXN * CAP];      // slotted CSR
__device__ float  g_dinv[MAXN];
__device__ float  g_s[MAXN];
__device__ float  g_bvec[F];
__device__ __half g_whi[F * F];                   // Wc' in B layout: [n][k]
__device__ __half g_t[(size_t)MAXN * F];          // x @ Wc' (UNSCALED, fp16)
__device__ __half g_t2[(size_t)MAXN * F];         // prescaled agg result

__device__ __forceinline__ void acc_h4(float4& acc, uint2 p) {
    float2 f0 = __half22float2(*(__half2*)&p.x);
    float2 f1 = __half22float2(*(__half2*)&p.y);
    acc.x += f0.x; acc.y += f0.y; acc.z += f1.x; acc.w += f1.y;
}
__device__ __forceinline__ void acc_h4f(float4& acc, uint2 p, float s) {
    float2 f0 = __half22float2(*(__half2*)&p.x);
    float2 f1 = __half22float2(*(__half2*)&p.y);
    acc.x = fmaf(f0.x, s, acc.x); acc.y = fmaf(f0.y, s, acc.y);
    acc.z = fmaf(f1.x, s, acc.z); acc.w = fmaf(f1.y, s, acc.w);
}

__device__ __forceinline__ void mma16816(
    float& d0, float& d1, float& d2, float& d3,
    uint32_t a0, uint32_t a1, uint32_t a2, uint32_t a3,
    uint32_t b0, uint32_t b1)
{
    asm volatile(
        "mma.sync.aligned.m16n8k16.row.col.f32.f16.f16.f32 "
        "{%0,%1,%2,%3}, {%4,%5,%6,%7}, {%8,%9}, {%0,%1,%2,%3};"
        : "+f"(d0), "+f"(d1), "+f"(d2), "+f"(d3)
        : "r"(a0), "r"(a1), "r"(a2), "r"(a3), "r"(b0), "r"(b1));
}
__device__ __forceinline__ void ldsm_x4(
    uint32_t& r0, uint32_t& r1, uint32_t& r2, uint32_t& r3, uint32_t addr)
{
    asm volatile(
        "ldmatrix.sync.aligned.m8n8.x4.shared.b16 {%0,%1,%2,%3}, [%4];"
        : "=r"(r0), "=r"(r1), "=r"(r2), "=r"(r3) : "r"(addr));
}

// --------------------------------------------------------------------------
// fill slotted CSR: 4 edges per thread via int4
__global__ void k_fill(const int* __restrict__ ei, int E) {
    int t = blockIdx.x * blockDim.x + threadIdx.x;
    int e4 = t * 4;
    if (e4 + 4 <= E) {
        int4 s = *(const int4*)(ei + e4);
        int4 d = *(const int4*)(ei + E + e4);
        int p0 = atomicAdd(&g_cur[d.x], 1);
        int p1 = atomicAdd(&g_cur[d.y], 1);
        int p2 = atomicAdd(&g_cur[d.z], 1);
        int p3 = atomicAdd(&g_cur[d.w], 1);
        g_csr[(size_t)d.x * CAP + p0] = s.x;
        g_csr[(size_t)d.y * CAP + p1] = s.y;
        g_csr[(size_t)d.z * CAP + p2] = s.z;
        g_csr[(size_t)d.w * CAP + p3] = s.w;
    } else {
        for (int e = e4; e < E; e++) {
            int dd = ei[E + e];
            int p = atomicAdd(&g_cur[dd], 1);
            g_csr[(size_t)dd * CAP + p] = ei[e];
        }
    }
}

__global__ void k_dinv(int n) {
    int i = blockIdx.x * blockDim.x + threadIdx.x;
    if (i < n) g_dinv[i] = rsqrtf((float)(g_cur[i] + 1));
}

// -------- Wc' = W1 @ [Wmu|Wls] -> [n][k] f16; bvec = b1 @ Wc --------------
__global__ void k_wc(const float* __restrict__ W1, const float* __restrict__ Wmu,
                     const float* __restrict__ Wls, const float* __restrict__ b1)
{
    int idx = blockIdx.x * blockDim.x + threadIdx.x;
    if (idx < F * F) {
        int k = idx >> 7, j = idx & 127;
        const float* wc = (j < 64) ? (Wmu + j) : (Wls + j - 64);
        const float* w1 = W1 + k * F;
        float s = 0.f;
        #pragma unroll 8
        for (int m = 0; m < F; m++) s = fmaf(w1[m], wc[m * 64], s);
        g_whi[j * F + k] = __float2half_rn(s);
    } else if (idx < F * F + F) {
        int j = idx - F * F;
        const float* wc = (j < 64) ? (Wmu + j) : (Wls + j - 64);
        float s = 0.f;
        #pragma unroll 8
        for (int m = 0; m < F; m++) s = fmaf(b1[m], wc[m * 64], s);
        g_bvec[j] = s;
    }
}

// -------- persistent pipelined HMMA GEMM: t = half(x @ Wc') ---------------
// 64-row tiles, double-buffered A in smem, register prefetch of next tile.
#define HG_SMEM ((128 + 2 * 64) * SPITCH * 2)

__global__ void __launch_bounds__(256, 2) k_hgemm(
    const float* __restrict__ A, __half* __restrict__ C, int M, int ntiles)
{
    extern __shared__ __half smem[];
    __half* sB = smem;                      // [128][SPITCH] weights
    __half* sA[2] = { sB + 128 * SPITCH,
                      sB + 128 * SPITCH + 64 * SPITCH };

    int tid = threadIdx.x;

    // weights once per CTA
    for (int i = tid * 4; i < F * F; i += 256 * 4) {
        int n = i >> 7, k = i & 127;
        *(uint2*)(sB + n * SPITCH + k) = *(const uint2*)(g_whi + i);
    }

    int wid = tid >> 5, lane = tid & 31;
    int qr = lane >> 2, qc = lane & 3;
    int wy = wid & 3, wx = wid >> 2;
    int rb = wy * 16;
    int cb = wx * 64;

    int li = lane & 7;
    int lm = lane >> 3;
    uint32_t a_off_bytes = (uint32_t)(((rb + (lm & 1) * 8 + li) * SPITCH
                                      + (lm >> 1) * 8) * 2);
    uint32_t a_base[2] = {
        (uint32_t)__cvta_generic_to_shared(sA[0]) + a_off_bytes,
        (uint32_t)__cvta_generic_to_shared(sA[1]) + a_off_bytes };
    uint32_t b_base[4];
    #pragma unroll
    for (int p = 0; p < 4; p++)
        b_base[p] = (uint32_t)__cvta_generic_to_shared(
            sB + (cb + p * 16 + (lm >> 1) * 8 + li) * SPITCH + (lm & 1) * 8);

    // per-thread prefetch slots: element idx = tid*4 + j*1024 of 64x128 tile
    int pr[8], pk[8];
    #pragma unroll
    for (int j = 0; j < 8; j++) {
        int idx = tid * 4 + j * 1024;
        pr[j] = idx >> 7; pk[j] = idx & 127;
    }

    float4 pf[8];
    int tile = blockIdx.x;
    if (tile >= ntiles) return;

    // prologue: load + store tile into buf0
    #pragma unroll
    for (int j = 0; j < 8; j++) {
        int r = tile * 64 + pr[j];
        pf[j] = (r < M) ? *(const float4*)(A + (size_t)r * F + pk[j])
                        : make_float4(0.f, 0.f, 0.f, 0.f);
    }
    #pragma unroll
    for (int j = 0; j < 8; j++) {
        __half2 h0 = __floats2half2_rn(pf[j].x, pf[j].y);
        __half2 h1 = __floats2half2_rn(pf[j].z, pf[j].w);
        uint2 o; o.x = *(uint32_t*)&h0; o.y = *(uint32_t*)&h1;
        *(uint2*)(sA[0] + pr[j] * SPITCH + pk[j]) = o;
    }
    __syncthreads();

    int cur = 0;
    while (true) {
        int next = tile + gridDim.x;
        bool has_next = (next < ntiles);
        if (has_next) {
            #pragma unroll
            for (int j = 0; j < 8; j++) {
                int r = next * 64 + pr[j];
                pf[j] = (r < M) ? *(const float4*)(A + (size_t)r * F + pk[j])
                                : make_float4(0.f, 0.f, 0.f, 0.f);
            }
        }

        // compute current tile
        float acc[8][4];
        #pragma unroll
        for (int t = 0; t < 8; t++)
            #pragma unroll
            for (int c = 0; c < 4; c++) acc[t][c] = 0.f;

        #pragma unroll
        for (int ks = 0; ks < 8; ks++) {
            uint32_t koff = ks * 16 * 2;
            uint32_t a0, a1, a2, a3;
            ldsm_x4(a0, a1, a2, a3, a_base[cur] + koff);
            #pragma unroll
            for (int p = 0; p < 4; p++) {
                uint32_t b0, b1, b2, b3;
                ldsm_x4(b0, b1, b2, b3, b_base[p] + koff);
                mma16816(acc[2*p][0], acc[2*p][1], acc[2*p][2], acc[2*p][3],
                         a0, a1, a2, a3, b0, b1);
                mma16816(acc[2*p+1][0], acc[2*p+1][1], acc[2*p+1][2], acc[2*p+1][3],
                         a0, a1, a2, a3, b2, b3);
            }
        }

        int r1 = tile * 64 + rb + qr;
        int r2 = r1 + 8;
        #pragma unroll
        for (int t = 0; t < 8; t++) {
            int col = cb + t * 8 + qc * 2;
            if (r1 < M) {
                __half2 h = __floats2half2_rn(acc[t][0], acc[t][1]);
                *(uint32_t*)(C + (size_t)r1 * F + col) = *(uint32_t*)&h;
            }
            if (r2 < M) {
                __half2 h = __floats2half2_rn(acc[t][2], acc[t][3]);
                *(uint32_t*)(C + (size_t)r2 * F + col) = *(uint32_t*)&h;
            }
        }

        if (!has_next) break;

        // store prefetched tile into alternate buffer
        #pragma unroll
        for (int j = 0; j < 8; j++) {
            __half2 h0 = __floats2half2_rn(pf[j].x, pf[j].y);
            __half2 h1 = __floats2half2_rn(pf[j].z, pf[j].w);
            uint2 o; o.x = *(uint32_t*)&h0; o.y = *(uint32_t*)&h1;
            *(uint2*)(sA[1 - cur] + pr[j] * SPITCH + pk[j]) = o;
        }
        __syncthreads();
        cur ^= 1;
        tile = next;
    }
}

// -------- aggregation A (scales gathered rows by dinv[src]) ---------------
__global__ void __launch_bounds__(256) k_aggA(
    const __half* __restrict__ feat, __half* __restrict__ out, int N)
{
    int w = (blockIdx.x * blockDim.x + threadIdx.x) >> 5;
    int lane = threadIdx.x & 31;
    if (w >= N) return;
    const uint2* f2 = (const uint2*)feat;
    float dv = g_dinv[w];
    float4 acc = make_float4(0.f, 0.f, 0.f, 0.f);
    acc_h4f(acc, f2[(size_t)w * 32 + lane], dv);   // self
    float sd = 0.f;
    const int* row = g_csr + (size_t)w * CAP;
    int cnt = g_cur[w];
    int e = 0;
    for (; e + 4 <= cnt; e += 4) {
        int s0 = row[e], s1 = row[e + 1], s2 = row[e + 2], s3 = row[e + 3];
        uint2 v0 = f2[(size_t)s0 * 32 + lane];
        uint2 v1 = f2[(size_t)s1 * 32 + lane];
        uint2 v2 = f2[(size_t)s2 * 32 + lane];
        uint2 v3 = f2[(size_t)s3 * 32 + lane];
        float d0 = g_dinv[s0], d1 = g_dinv[s1], d2 = g_dinv[s2], d3 = g_dinv[s3];
        sd += d0 + d1 + d2 + d3;
        acc_h4f(acc, v0, d0); acc_h4f(acc, v1, d1);
        acc_h4f(acc, v2, d2); acc_h4f(acc, v3, d3);
    }
    for (; e < cnt; e++) {
        int s = row[e];
        float ds = g_dinv[s];
        sd += ds;
        acc_h4f(acc, f2[(size_t)s * 32 + lane], ds);
    }
    float d2 = dv * dv;
    __half2 h0 = __floats2half2_rn(acc.x * d2, acc.y * d2);
    __half2 h1 = __floats2half2_rn(acc.z * d2, acc.w * d2);
    uint2 o; o.x = *(unsigned*)&h0; o.y = *(unsigned*)&h1;
    ((uint2*)out)[(size_t)w * 32 + lane] = o;
    if (lane == 0) g_s[w] = dv * (dv + sd);
}

// -------- aggregation B + bias + reparametrize ----------
__global__ void __launch_bounds__(256) k_aggB(
    const __half* __restrict__ feat, const float* __restrict__ bmu,
    const float* __restrict__ bls, const float* __restrict__ init,
    float* __restrict__ out, int N)
{
    int w = (blockIdx.x * blockDim.x + threadIdx.x) >> 5;
    int lane = threadIdx.x & 31;
    if (w >= N) return;
    const uint2* f2 = (const uint2*)feat;
    float4 acc = make_float4(0.f, 0.f, 0.f, 0.f);
    acc_h4(acc, f2[(size_t)w * 32 + lane]);   // self (prescaled)
    const int* row = g_csr + (size_t)w * CAP;
    int cnt = g_cur[w];
    int e = 0;
    for (; e + 4 <= cnt; e += 4) {
        int s0 = row[e], s1 = row[e + 1], s2 = row[e + 2], s3 = row[e + 3];
        uint2 v0 = f2[(size_t)s0 * 32 + lane];
        uint2 v1 = f2[(size_t)s1 * 32 + lane];
        uint2 v2 = f2[(size_t)s2 * 32 + lane];
        uint2 v3 = f2[(size_t)s3 * 32 + lane];
        acc_h4(acc, v0); acc_h4(acc, v1); acc_h4(acc, v2); acc_h4(acc, v3);
    }
    for (; e < cnt; e++)
        acc_h4(acc, f2[(size_t)row[e] * 32 + lane]);

    float dv = g_dinv[w];
    float si = g_s[w];
    float4 b = (lane < 16) ? ((const float4*)bmu)[lane]
                           : ((const float4*)bls)[lane - 16];
    float4 bv = ((const float4*)g_bvec)[lane];
    float4 v = make_float4(acc.x * dv + si * bv.x + b.x,
                           acc.y * dv + si * bv.y + b.y,
                           acc.z * dv + si * bv.z + b.z,
                           acc.w * dv + si * bv.w + b.w);
    float lx = __shfl_xor_sync(0xffffffffu, v.x, 16);
    float ly = __shfl_xor_sync(0xffffffffu, v.y, 16);
    float lz = __shfl_xor_sync(0xffffffffu, v.z, 16);
    float lw = __shfl_xor_sync(0xffffffffu, v.w, 16);
    if (lane < 16) {
        float4 id = ((const float4*)init)[(size_t)w * 16 + lane];
        float4 r = make_float4(v.x + id.x * expf(lx),
                               v.y + id.y * expf(ly),
                               v.z + id.z * expf(lz),
                               v.w + id.w * expf(lw));
        ((float4*)out)[(size_t)w * 16 + lane] = r;
    }
}

// --------------------------------------------------------------------------
extern "C" void kernel_launch(void* const* d_in, const int* in_sizes, int n_in,
                              void* d_out, int out_size)
{
    const float* x    = (const float*)d_in[0];
    const int*   ei   = (const int*)d_in[1];
    const float* init = (const float*)d_in[2];
    const float* W1   = (const float*)d_in[3];
    const float* b1   = (const float*)d_in[4];
    const float* Wmu  = (const float*)d_in[5];
    const float* bmu  = (const float*)d_in[6];
    const float* Wls  = (const float*)d_in[7];
    const float* bls  = (const float*)d_in[8];
    float* out = (float*)d_out;

    int N = in_sizes[0] / F;
    int E = in_sizes[1] / 2;
    int ne4 = (E / 4 + 255) / 256;

    static cudaStream_t s2 = nullptr;
    static cudaEvent_t evFork = nullptr, evJoin = nullptr;
    if (!s2) {
        cudaStreamCreate(&s2);
        cudaEventCreateWithFlags(&evFork, cudaEventDisableTiming);
        cudaEventCreateWithFlags(&evJoin, cudaEventDisableTiming);
        cudaFuncSetAttribute(k_hgemm,
            cudaFuncAttributeMaxDynamicSharedMemorySize, HG_SMEM);
    }

    int *cur; __half *t, *t2;
    cudaGetSymbolAddress((void**)&cur, g_cur);
    cudaGetSymbolAddress((void**)&t,  g_t);
    cudaGetSymbolAddress((void**)&t2, g_t2);

    // fork: CSR build chain on s2, concurrent with wc+hgemm on main stream
    cudaEventRecord(evFork, 0);
    cudaStreamWaitEvent(s2, evFork, 0);
    cudaMemsetAsync(cur, 0, (size_t)N * sizeof(int), s2);
    k_fill<<<ne4, 256, 0, s2>>>(ei, E);
    k_dinv<<<(N + 255) / 256, 256, 0, s2>>>(N);
    cudaEventRecord(evJoin, s2);

    // main stream: weights + persistent GEMM
    k_wc<<<(F * F + F + 255) / 256, 256>>>(W1, Wmu, Wls, b1);
    int ntiles = (N + 63) / 64;
    int gemm_grid = ntiles < 296 ? ntiles : 296;
    k_hgemm<<<gemm_grid, 256, HG_SMEM>>>(x, t, N, ntiles);

    // join, then aggregations
    cudaStreamWaitEvent(0, evJoin, 0);
    int agg_grid = (N * 32 + 255) / 256;
    k_aggA<<<agg_grid, 256>>>(t, t2, N);
    k_aggB<<<agg_grid, 256>>>(t2, bmu, bls, init, out, N);
}

// round 15
// speedup vs baseline: 1.1106x; 1.0174x over previous
#include <cuda_runtime.h>
#include <cuda_fp16.h>
#include <cstdint>

#define MAXN 100000
#define MAXE 1600000
#define F 128
#define CAP 96       // fixed CSR slot capacity per node (P(deg>96) ~ 0)
#define SPITCH 136   // halfs per smem row (conflict-free LDS + LDSM)

// -------- scratch ----------
__device__ int    g_cur[MAXN];                    // in-degree counters / cursors
__device__ int    g_csr[(size_t)MAXN * CAP];      // slotted CSR
__device__ float  g_dinv[MAXN];
__device__ float  g_s[MAXN];
__device__ float  g_bvec[F];
__device__ __half g_whi[F * F];                   // Wc' in B layout: [n][k]
__device__ __half g_t[(size_t)MAXN * F];          // x @ Wc' (UNSCALED, fp16)
__device__ __half g_t2[(size_t)MAXN * F];         // prescaled agg result

__device__ __forceinline__ void acc_h4(float4& acc, uint2 p) {
    float2 f0 = __half22float2(*(__half2*)&p.x);
    float2 f1 = __half22float2(*(__half2*)&p.y);
    acc.x += f0.x; acc.y += f0.y; acc.z += f1.x; acc.w += f1.y;
}
__device__ __forceinline__ void acc_h4f(float4& acc, uint2 p, float s) {
    float2 f0 = __half22float2(*(__half2*)&p.x);
    float2 f1 = __half22float2(*(__half2*)&p.y);
    acc.x = fmaf(f0.x, s, acc.x); acc.y = fmaf(f0.y, s, acc.y);
    acc.z = fmaf(f1.x, s, acc.z); acc.w = fmaf(f1.y, s, acc.w);
}

__device__ __forceinline__ void mma16816(
    float& d0, float& d1, float& d2, float& d3,
    uint32_t a0, uint32_t a1, uint32_t a2, uint32_t a3,
    uint32_t b0, uint32_t b1)
{
    asm volatile(
        "mma.sync.aligned.m16n8k16.row.col.f32.f16.f16.f32 "
        "{%0,%1,%2,%3}, {%4,%5,%6,%7}, {%8,%9}, {%0,%1,%2,%3};"
        : "+f"(d0), "+f"(d1), "+f"(d2), "+f"(d3)
        : "r"(a0), "r"(a1), "r"(a2), "r"(a3), "r"(b0), "r"(b1));
}
__device__ __forceinline__ void ldsm_x4(
    uint32_t& r0, uint32_t& r1, uint32_t& r2, uint32_t& r3, uint32_t addr)
{
    asm volatile(
        "ldmatrix.sync.aligned.m8n8.x4.shared.b16 {%0,%1,%2,%3}, [%4];"
        : "=r"(r0), "=r"(r1), "=r"(r2), "=r"(r3) : "r"(addr));
}

// --------------------------------------------------------------------------
// fill slotted CSR: 4 edges per thread via int4
__global__ void k_fill(const int* __restrict__ ei, int E) {
    int t = blockIdx.x * blockDim.x + threadIdx.x;
    int e4 = t * 4;
    if (e4 + 4 <= E) {
        int4 s = *(const int4*)(ei + e4);
        int4 d = *(const int4*)(ei + E + e4);
        int p0 = atomicAdd(&g_cur[d.x], 1);
        int p1 = atomicAdd(&g_cur[d.y], 1);
        int p2 = atomicAdd(&g_cur[d.z], 1);
        int p3 = atomicAdd(&g_cur[d.w], 1);
        g_csr[(size_t)d.x * CAP + p0] = s.x;
        g_csr[(size_t)d.y * CAP + p1] = s.y;
        g_csr[(size_t)d.z * CAP + p2] = s.z;
        g_csr[(size_t)d.w * CAP + p3] = s.w;
    } else {
        for (int e = e4; e < E; e++) {
            int dd = ei[E + e];
            int p = atomicAdd(&g_cur[dd], 1);
            g_csr[(size_t)dd * CAP + p] = ei[e];
        }
    }
}

__global__ void k_dinv(int n) {
    int i = blockIdx.x * blockDim.x + threadIdx.x;
    if (i < n) g_dinv[i] = rsqrtf((float)(g_cur[i] + 1));
}

// -------- Wc' = W1 @ [Wmu|Wls] -> [n][k] f16; bvec = b1 @ Wc --------------
__global__ void k_wc(const float* __restrict__ W1, const float* __restrict__ Wmu,
                     const float* __restrict__ Wls, const float* __restrict__ b1)
{
    int idx = blockIdx.x * blockDim.x + threadIdx.x;
    if (idx < F * F) {
        int k = idx >> 7, j = idx & 127;
        const float* wc = (j < 64) ? (Wmu + j) : (Wls + j - 64);
        const float* w1 = W1 + k * F;
        float s = 0.f;
        #pragma unroll 8
        for (int m = 0; m < F; m++) s = fmaf(w1[m], wc[m * 64], s);
        g_whi[j * F + k] = __float2half_rn(s);
    } else if (idx < F * F + F) {
        int j = idx - F * F;
        const float* wc = (j < 64) ? (Wmu + j) : (Wls + j - 64);
        float s = 0.f;
        #pragma unroll 8
        for (int m = 0; m < F; m++) s = fmaf(b1[m], wc[m * 64], s);
        g_bvec[j] = s;
    }
}

// -------- persistent deep-pipelined HMMA GEMM: t = half(x @ Wc') ----------
// 512 threads, 1 CTA/SM, 64-row tiles, 3-buffer smem ring,
// load->use distance = 2 iterations.
#define HG_SMEM ((128 + 3 * 64) * SPITCH * 2)

__global__ void __launch_bounds__(512, 1) k_hgemm(
    const float* __restrict__ A, __half* __restrict__ C, int M, int ntiles)
{
    extern __shared__ __half smem[];
    __half* sB = smem;                          // [128][SPITCH] weights
    __half* sA[3] = { sB + 128 * SPITCH,
                      sB + (128 + 64) * SPITCH,
                      sB + (128 + 128) * SPITCH };

    int tid = threadIdx.x;

    // weights once per CTA
    for (int i = tid * 4; i < F * F; i += 512 * 4) {
        int n = i >> 7, k = i & 127;
        *(uint2*)(sB + n * SPITCH + k) = *(const uint2*)(g_whi + i);
    }

    int wid = tid >> 5, lane = tid & 31;
    int qr = lane >> 2, qc = lane & 3;
    int wy = wid & 3, wx = wid >> 2;            // 4x4 warp grid
    int rb = wy * 16;                            // rows rb..rb+15
    int cb = wx * 32;                            // cols cb..cb+31

    int li = lane & 7;
    int lm = lane >> 3;
    uint32_t a_off = (uint32_t)(((rb + (lm & 1) * 8 + li) * SPITCH
                                + (lm >> 1) * 8) * 2);
    uint32_t a_base[3];
    #pragma unroll
    for (int b = 0; b < 3; b++)
        a_base[b] = (uint32_t)__cvta_generic_to_shared(sA[b]) + a_off;
    uint32_t b_base[2];
    #pragma unroll
    for (int p = 0; p < 2; p++)
        b_base[p] = (uint32_t)__cvta_generic_to_shared(
            sB + (cb + p * 16 + (lm >> 1) * 8 + li) * SPITCH + (lm & 1) * 8);

    // per-thread prefetch slots: 4 float4 (16 floats) of the 64x128 tile
    int pr[4], pk[4];
    #pragma unroll
    for (int j = 0; j < 4; j++) {
        int idx = tid * 4 + j * 2048;
        pr[j] = idx >> 7; pk[j] = idx & 127;
    }

    int tile = blockIdx.x;
    if (tile >= ntiles) return;

    float4 pf[4];
    // prologue: tile -> buf0; start load of tile+stride
    #pragma unroll
    for (int j = 0; j < 4; j++) {
        int r = tile * 64 + pr[j];
        pf[j] = (r < M) ? *(const float4*)(A + (size_t)r * F + pk[j])
                        : make_float4(0.f, 0.f, 0.f, 0.f);
    }
    #pragma unroll
    for (int j = 0; j < 4; j++) {
        __half2 h0 = __floats2half2_rn(pf[j].x, pf[j].y);
        __half2 h1 = __floats2half2_rn(pf[j].z, pf[j].w);
        uint2 o; o.x = *(uint32_t*)&h0; o.y = *(uint32_t*)&h1;
        *(uint2*)(sA[0] + pr[j] * SPITCH + pk[j]) = o;
    }
    int nxt = tile + gridDim.x;
    bool have_nxt = (nxt < ntiles);
    if (have_nxt) {
        #pragma unroll
        for (int j = 0; j < 4; j++) {
            int r = nxt * 64 + pr[j];
            pf[j] = (r < M) ? *(const float4*)(A + (size_t)r * F + pk[j])
                            : make_float4(0.f, 0.f, 0.f, 0.f);
        }
    }
    __syncthreads();

    int cur = 0;
    while (true) {
        // stage tile nxt (regs -> next ring buffer), then issue loads for nxt+stride
        int buf_nxt = (cur == 2) ? 0 : cur + 1;
        int nn = nxt + gridDim.x;
        if (have_nxt) {
            #pragma unroll
            for (int j = 0; j < 4; j++) {
                __half2 h0 = __floats2half2_rn(pf[j].x, pf[j].y);
                __half2 h1 = __floats2half2_rn(pf[j].z, pf[j].w);
                uint2 o; o.x = *(uint32_t*)&h0; o.y = *(uint32_t*)&h1;
                *(uint2*)(sA[buf_nxt] + pr[j] * SPITCH + pk[j]) = o;
            }
            if (nn < ntiles) {
                #pragma unroll
                for (int j = 0; j < 4; j++) {
                    int r = nn * 64 + pr[j];
                    pf[j] = (r < M) ? *(const float4*)(A + (size_t)r * F + pk[j])
                                    : make_float4(0.f, 0.f, 0.f, 0.f);
                }
            }
        }

        // compute current tile from buf cur
        float acc[4][4];
        #pragma unroll
        for (int t = 0; t < 4; t++)
            #pragma unroll
            for (int c = 0; c < 4; c++) acc[t][c] = 0.f;

        #pragma unroll
        for (int ks = 0; ks < 8; ks++) {
            uint32_t koff = ks * 16 * 2;
            uint32_t a0, a1, a2, a3;
            ldsm_x4(a0, a1, a2, a3, a_base[cur] + koff);
            #pragma unroll
            for (int p = 0; p < 2; p++) {
                uint32_t b0, b1, b2, b3;
                ldsm_x4(b0, b1, b2, b3, b_base[p] + koff);
                mma16816(acc[2*p][0], acc[2*p][1], acc[2*p][2], acc[2*p][3],
                         a0, a1, a2, a3, b0, b1);
                mma16816(acc[2*p+1][0], acc[2*p+1][1], acc[2*p+1][2], acc[2*p+1][3],
                         a0, a1, a2, a3, b2, b3);
            }
        }

        int r1 = tile * 64 + rb + qr;
        int r2 = r1 + 8;
        #pragma unroll
        for (int t = 0; t < 4; t++) {
            int col = cb + t * 8 + qc * 2;
            if (r1 < M) {
                __half2 h = __floats2half2_rn(acc[t][0], acc[t][1]);
                *(uint32_t*)(C + (size_t)r1 * F + col) = *(uint32_t*)&h;
            }
            if (r2 < M) {
                __half2 h = __floats2half2_rn(acc[t][2], acc[t][3]);
                *(uint32_t*)(C + (size_t)r2 * F + col) = *(uint32_t*)&h;
            }
        }

        if (!have_nxt) break;
        __syncthreads();
        tile = nxt;
        nxt = nn;
        have_nxt = (nxt < ntiles);
        cur = buf_nxt;
    }
}

// -------- aggregation A (scales gathered rows by dinv[src]) ---------------
__global__ void __launch_bounds__(256) k_aggA(
    const __half* __restrict__ feat, __half* __restrict__ out, int N)
{
    int w = (blockIdx.x * blockDim.x + threadIdx.x) >> 5;
    int lane = threadIdx.x & 31;
    if (w >= N) return;
    const uint2* f2 = (const uint2*)feat;
    float dv = g_dinv[w];
    float4 acc = make_float4(0.f, 0.f, 0.f, 0.f);
    acc_h4f(acc, f2[(size_t)w * 32 + lane], dv);   // self
    float sd = 0.f;
    const int* row = g_csr + (size_t)w * CAP;
    int cnt = g_cur[w];
    int e = 0;
    for (; e + 4 <= cnt; e += 4) {
        int s0 = row[e], s1 = row[e + 1], s2 = row[e + 2], s3 = row[e + 3];
        uint2 v0 = f2[(size_t)s0 * 32 + lane];
        uint2 v1 = f2[(size_t)s1 * 32 + lane];
        uint2 v2 = f2[(size_t)s2 * 32 + lane];
        uint2 v3 = f2[(size_t)s3 * 32 + lane];
        float d0 = g_dinv[s0], d1 = g_dinv[s1], d2 = g_dinv[s2], d3 = g_dinv[s3];
        sd += d0 + d1 + d2 + d3;
        acc_h4f(acc, v0, d0); acc_h4f(acc, v1, d1);
        acc_h4f(acc, v2, d2); acc_h4f(acc, v3, d3);
    }
    for (; e < cnt; e++) {
        int s = row[e];
        float ds = g_dinv[s];
        sd += ds;
        acc_h4f(acc, f2[(size_t)s * 32 + lane], ds);
    }
    float d2 = dv * dv;
    __half2 h0 = __floats2half2_rn(acc.x * d2, acc.y * d2);
    __half2 h1 = __floats2half2_rn(acc.z * d2, acc.w * d2);
    uint2 o; o.x = *(unsigned*)&h0; o.y = *(unsigned*)&h1;
    ((uint2*)out)[(size_t)w * 32 + lane] = o;
    if (lane == 0) g_s[w] = dv * (dv + sd);
}

// -------- aggregation B + bias + reparametrize ----------
__global__ void __launch_bounds__(256) k_aggB(
    const __half* __restrict__ feat, const float* __restrict__ bmu,
    const float* __restrict__ bls, const float* __restrict__ init,
    float* __restrict__ out, int N)
{
    int w = (blockIdx.x * blockDim.x + threadIdx.x) >> 5;
    int lane = threadIdx.x & 31;
    if (w >= N) return;
    const uint2* f2 = (const uint2*)feat;
    float4 acc = make_float4(0.f, 0.f, 0.f, 0.f);
    acc_h4(acc, f2[(size_t)w * 32 + lane]);   // self (prescaled)
    const int* row = g_csr + (size_t)w * CAP;
    int cnt = g_cur[w];
    int e = 0;
    for (; e + 4 <= cnt; e += 4) {
        int s0 = row[e], s1 = row[e + 1], s2 = row[e + 2], s3 = row[e + 3];
        uint2 v0 = f2[(size_t)s0 * 32 + lane];
        uint2 v1 = f2[(size_t)s1 * 32 + lane];
        uint2 v2 = f2[(size_t)s2 * 32 + lane];
        uint2 v3 = f2[(size_t)s3 * 32 + lane];
        acc_h4(acc, v0); acc_h4(acc, v1); acc_h4(acc, v2); acc_h4(acc, v3);
    }
    for (; e < cnt; e++)
        acc_h4(acc, f2[(size_t)row[e] * 32 + lane]);

    float dv = g_dinv[w];
    float si = g_s[w];
    float4 b = (lane < 16) ? ((const float4*)bmu)[lane]
                           : ((const float4*)bls)[lane - 16];
    float4 bv = ((const float4*)g_bvec)[lane];
    float4 v = make_float4(acc.x * dv + si * bv.x + b.x,
                           acc.y * dv + si * bv.y + b.y,
                           acc.z * dv + si * bv.z + b.z,
                           acc.w * dv + si * bv.w + b.w);
    float lx = __shfl_xor_sync(0xffffffffu, v.x, 16);
    float ly = __shfl_xor_sync(0xffffffffu, v.y, 16);
    float lz = __shfl_xor_sync(0xffffffffu, v.z, 16);
    float lw = __shfl_xor_sync(0xffffffffu, v.w, 16);
    if (lane < 16) {
        float4 id = ((const float4*)init)[(size_t)w * 16 + lane];
        float4 r = make_float4(v.x + id.x * expf(lx),
                               v.y + id.y * expf(ly),
                               v.z + id.z * expf(lz),
                               v.w + id.w * expf(lw));
        ((float4*)out)[(size_t)w * 16 + lane] = r;
    }
}

// --------------------------------------------------------------------------
extern "C" void kernel_launch(void* const* d_in, const int* in_sizes, int n_in,
                              void* d_out, int out_size)
{
    const float* x    = (const float*)d_in[0];
    const int*   ei   = (const int*)d_in[1];
    const float* init = (const float*)d_in[2];
    const float* W1   = (const float*)d_in[3];
    const float* b1   = (const float*)d_in[4];
    const float* Wmu  = (const float*)d_in[5];
    const float* bmu  = (const float*)d_in[6];
    const float* Wls  = (const float*)d_in[7];
    const float* bls  = (const float*)d_in[8];
    float* out = (float*)d_out;

    int N = in_sizes[0] / F;
    int E = in_sizes[1] / 2;
    int ne4 = (E / 4 + 255) / 256;

    static cudaStream_t s2 = nullptr;
    static cudaEvent_t evFork = nullptr, evJoin = nullptr;
    if (!s2) {
        cudaStreamCreate(&s2);
        cudaEventCreateWithFlags(&evFork, cudaEventDisableTiming);
        cudaEventCreateWithFlags(&evJoin, cudaEventDisableTiming);
        cudaFuncSetAttribute(k_hgemm,
            cudaFuncAttributeMaxDynamicSharedMemorySize, HG_SMEM);
    }

    int *cur; __half *t, *t2;
    cudaGetSymbolAddress((void**)&cur, g_cur);
    cudaGetSymbolAddress((void**)&t,  g_t);
    cudaGetSymbolAddress((void**)&t2, g_t2);

    // fork: CSR build chain on s2, concurrent with wc+hgemm on main stream
    cudaEventRecord(evFork, 0);
    cudaStreamWaitEvent(s2, evFork, 0);
    cudaMemsetAsync(cur, 0, (size_t)N * sizeof(int), s2);
    k_fill<<<ne4, 256, 0, s2>>>(ei, E);
    k_dinv<<<(N + 255) / 256, 256, 0, s2>>>(N);
    cudaEventRecord(evJoin, s2);

    // main stream: weights + persistent GEMM
    k_wc<<<(F * F + F + 255) / 256, 256>>>(W1, Wmu, Wls, b1);
    int ntiles = (N + 63) / 64;
    int gemm_grid = ntiles < 148 ? ntiles : 148;
    k_hgemm<<<gemm_grid, 512, HG_SMEM>>>(x, t, N, ntiles);

    // join, then aggregations
    cudaStreamWaitEvent(0, evJoin, 0);
    int agg_grid = (N * 32 + 255) / 256;
    k_aggA<<<agg_grid, 256>>>(t, t2, N);
    k_aggB<<<agg_grid, 256>>>(t2, bmu, bls, init, out, N);
}